// round 1
// baseline (speedup 1.0000x reference)
#include <cuda_runtime.h>

// Problem constants
#define B_    8
#define N_    8192
#define S_    2048
#define D1_   128
#define D2_   256
#define C0_   384          // D1 + D2
#define O1_   256
#define O2_   128
#define ROWS_ 65536        // B_ * N_
#define BN_EPS_ 1e-5f

typedef unsigned long long ull;

// ---------------- device scratch (no cudaMalloc allowed) ----------------
__device__ __align__(16) float g_X [(size_t)ROWS_ * C0_];   // concat [row][384]
__device__ __align__(16) float g_Y1[(size_t)ROWS_ * O1_];   // layer1 pre-BN
__device__ __align__(16) float g_Y2[(size_t)ROWS_ * O2_];   // layer2 pre-BN
__device__ __align__(16) float g_f2[(size_t)B_ * S_ * D2_]; // points2 transposed [b][s][d]
__device__ float4 g_p2[B_ * S_];                            // (x,y,z,|p|^2)
__device__ int    g_idx3[ROWS_ * 3];
__device__ float  g_w3 [ROWS_ * 3];
__device__ float  g_stats1[2 * O1_];
__device__ float  g_stats2[2 * O2_];
__device__ float  g_sc1[O1_], g_sh1[O1_];
__device__ float  g_sc2[O2_], g_sh2[O2_];

// ---------------- packed fp32x2 helpers (sm_100+) ----------------
__device__ __forceinline__ ull pack2(float lo, float hi) {
    ull r; asm("mov.b64 %0, {%1, %2};" : "=l"(r) : "f"(lo), "f"(hi)); return r;
}
__device__ __forceinline__ void unpack2(ull v, float& lo, float& hi) {
    asm("mov.b64 {%0, %1}, %2;" : "=f"(lo), "=f"(hi) : "l"(v));
}
__device__ __forceinline__ void ffma2(ull& c, ull a, ull b) {
    asm("fma.rn.f32x2 %0, %1, %2, %0;" : "+l"(c) : "l"(a), "l"(b));
}

// ---------------- prep: pack xyz2 + zero stats ----------------
__global__ void k_prep(const float* __restrict__ xyz2) {
    int t = blockIdx.x * 256 + threadIdx.x;
    if (t < 2 * O1_) g_stats1[t] = 0.f;
    if (t < 2 * O2_) g_stats2[t] = 0.f;
    if (t < B_ * S_) {
        int b = t / S_, s = t % S_;
        const float* p = xyz2 + (size_t)b * 3 * S_;
        float x = p[s], y = p[S_ + s], z = p[2 * S_ + s];
        g_p2[t] = make_float4(x, y, z, x * x + y * y + z * z);
    }
}

// ---------------- transpose points2 [B][D2][S] -> g_f2 [B][S][D2] ----------------
__global__ void k_tr_f2(const float* __restrict__ p2) {
    __shared__ float tile[32][33];
    int b = blockIdx.z;
    int s0 = blockIdx.x * 32, d0 = blockIdx.y * 32;
    int tx = threadIdx.x, ty = threadIdx.y;
    const float* src = p2 + ((size_t)b * D2_ + d0) * S_ + s0;
    #pragma unroll
    for (int i = ty; i < 32; i += 8)
        tile[i][tx] = src[(size_t)i * S_ + tx];          // (d0+i, s0+tx)
    __syncthreads();
    float* dst = g_f2 + ((size_t)b * S_ + s0) * D2_ + d0;
    #pragma unroll
    for (int i = ty; i < 32; i += 8)
        dst[(size_t)i * D2_ + tx] = tile[tx][i];          // (s0+i, d0+tx)
}

// ---------------- transpose points1 [B][D1][N] -> g_X[:, 0:128] ----------------
__global__ void k_tr_f1(const float* __restrict__ p1) {
    __shared__ float tile[32][33];
    int b = blockIdx.z;
    int n0 = blockIdx.x * 32, d0 = blockIdx.y * 32;
    int tx = threadIdx.x, ty = threadIdx.y;
    const float* src = p1 + ((size_t)b * D1_ + d0) * N_ + n0;
    #pragma unroll
    for (int i = ty; i < 32; i += 8)
        tile[i][tx] = src[(size_t)i * N_ + tx];
    __syncthreads();
    float* dst = g_X + ((size_t)(b * N_ + n0)) * C0_ + d0;
    #pragma unroll
    for (int i = ty; i < 32; i += 8)
        dst[(size_t)i * C0_ + tx] = tile[tx][i];
}

// ---------------- 3-NN per (b,n) ----------------
__global__ __launch_bounds__(256) void k_nn3(const float* __restrict__ xyz1) {
    __shared__ float4 sp[S_];   // 32 KB
    int b = blockIdx.y;
    int n = blockIdx.x * 256 + threadIdx.x;
    for (int i = threadIdx.x; i < S_; i += 256) sp[i] = g_p2[b * S_ + i];
    __syncthreads();

    const float* q = xyz1 + (size_t)b * 3 * N_;
    float x = q[n], y = q[N_ + n], z = q[2 * N_ + n];
    float nx = -2.f * x, ny = -2.f * y, nz = -2.f * z;

    float d0 = 1e30f, d1 = 1e30f, d2 = 1e30f;
    int i0 = 0, i1 = 0, i2 = 0;
    #pragma unroll 4
    for (int s = 0; s < S_; s++) {
        float4 p = sp[s];
        float d = fmaf(p.x, nx, fmaf(p.y, ny, fmaf(p.z, nz, p.w)));
        if (d < d2) {
            if (d < d1) {
                d2 = d1; i2 = i1;
                if (d < d0) { d1 = d0; i1 = i0; d0 = d; i0 = s; }
                else        { d1 = d;  i1 = s; }
            } else { d2 = d; i2 = s; }
        }
    }
    float r1 = x * x + y * y + z * z;
    float t0 = fmaxf(d0 + r1, 1e-10f);
    float t1 = fmaxf(d1 + r1, 1e-10f);
    float t2 = fmaxf(d2 + r1, 1e-10f);
    float w0 = 1.f / t0, w1 = 1.f / t1, w2 = 1.f / t2;
    float inv = 1.f / (w0 + w1 + w2);
    size_t row = (size_t)b * N_ + n;
    g_idx3[row * 3 + 0] = i0; g_idx3[row * 3 + 1] = i1; g_idx3[row * 3 + 2] = i2;
    g_w3 [row * 3 + 0] = w0 * inv; g_w3[row * 3 + 1] = w1 * inv; g_w3[row * 3 + 2] = w2 * inv;
}

// ---------------- gather + interpolate -> g_X[:, 128:384] ----------------
__global__ void k_interp() {
    unsigned row = blockIdx.x;          // 0..65535
    int d = threadIdx.x;                // 0..255
    int b = row / N_;
    int  i0 = g_idx3[(size_t)row * 3 + 0];
    int  i1 = g_idx3[(size_t)row * 3 + 1];
    int  i2 = g_idx3[(size_t)row * 3 + 2];
    float w0 = g_w3[(size_t)row * 3 + 0];
    float w1 = g_w3[(size_t)row * 3 + 1];
    float w2 = g_w3[(size_t)row * 3 + 2];
    const float* f = g_f2 + (size_t)b * S_ * D2_;
    float v = w0 * f[(size_t)i0 * D2_ + d]
            + w1 * f[(size_t)i1 * D2_ + d]
            + w2 * f[(size_t)i2 * D2_ + d];
    g_X[(size_t)row * C0_ + D1_ + d] = v;
}

// ---------------- fused GEMM (+ BN-ReLU on A for layer 2) + channel stats ----------------
__device__ __forceinline__ void compute_tile(const float (*Asb)[132], const float (*Bsb)[132],
                                             ull cc[4][8], int tx, int ty) {
    #pragma unroll
    for (int k = 0; k < 16; k++) {
        float4 a0 = *(const float4*)&Asb[k][ty * 4];
        float4 a1 = *(const float4*)&Asb[k][ty * 4 + 64];
        float4 b0 = *(const float4*)&Bsb[k][tx * 4];
        float4 b1 = *(const float4*)&Bsb[k][tx * 4 + 64];
        ull ap0 = pack2(a0.x, a0.y), ap1 = pack2(a0.z, a0.w);
        ull ap2 = pack2(a1.x, a1.y), ap3 = pack2(a1.z, a1.w);
        ull bd[8];
        bd[0] = pack2(b0.x, b0.x); bd[1] = pack2(b0.y, b0.y);
        bd[2] = pack2(b0.z, b0.z); bd[3] = pack2(b0.w, b0.w);
        bd[4] = pack2(b1.x, b1.x); bd[5] = pack2(b1.y, b1.y);
        bd[6] = pack2(b1.z, b1.z); bd[7] = pack2(b1.w, b1.w);
        #pragma unroll
        for (int j = 0; j < 8; j++) {
            ffma2(cc[0][j], ap0, bd[j]);
            ffma2(cc[1][j], ap1, bd[j]);
            ffma2(cc[2][j], ap2, bd[j]);
            ffma2(cc[3][j], ap3, bd[j]);
        }
    }
}

template<bool FIRST>
__global__ __launch_bounds__(256) void k_gemm(const float* __restrict__ W,
                                              const float* __restrict__ bias) {
    constexpr int KD = FIRST ? C0_ : O1_;
    constexpr int SC = FIRST ? O1_ : O2_;
    const float* __restrict__ A = FIRST ? g_X : g_Y1;
    float* __restrict__ Y       = FIRST ? g_Y1 : g_Y2;
    float* __restrict__ stats   = FIRST ? g_stats1 : g_stats2;

    __shared__ __align__(16) float As[2][16][132];
    __shared__ __align__(16) float Bs[2][16][132];

    const int tid = threadIdx.x;
    const int tx = tid & 15, ty = tid >> 4;
    const int ar = tid >> 2, akv = tid & 3;

    const float* Ap0 = A + (size_t)(blockIdx.x * 128 + ar) * KD + akv * 4;
    const float* Ap1 = Ap0 + (size_t)64 * KD;
    const float* Wp0 = W + (size_t)(blockIdx.y * 128 + ar) * KD + akv * 4;
    const float* Wp1 = Wp0 + (size_t)64 * KD;

    ull cc[4][8];
    #pragma unroll
    for (int p = 0; p < 4; p++)
        #pragma unroll
        for (int j = 0; j < 8; j++) cc[p][j] = 0ull;

    float4 a0r, a1r, w0r, w1r;

#define LOADSTAGE(kt) do {                                                     \
        a0r = *(const float4*)(Ap0 + (kt));                                    \
        a1r = *(const float4*)(Ap1 + (kt));                                    \
        w0r = *(const float4*)(Wp0 + (kt));                                    \
        w1r = *(const float4*)(Wp1 + (kt));                                    \
        if (!FIRST) {                                                          \
            float4 sc = *(const float4*)(g_sc1 + (kt) + akv * 4);              \
            float4 sh = *(const float4*)(g_sh1 + (kt) + akv * 4);              \
            a0r.x = fmaxf(fmaf(a0r.x, sc.x, sh.x), 0.f);                       \
            a0r.y = fmaxf(fmaf(a0r.y, sc.y, sh.y), 0.f);                       \
            a0r.z = fmaxf(fmaf(a0r.z, sc.z, sh.z), 0.f);                       \
            a0r.w = fmaxf(fmaf(a0r.w, sc.w, sh.w), 0.f);                       \
            a1r.x = fmaxf(fmaf(a1r.x, sc.x, sh.x), 0.f);                       \
            a1r.y = fmaxf(fmaf(a1r.y, sc.y, sh.y), 0.f);                       \
            a1r.z = fmaxf(fmaf(a1r.z, sc.z, sh.z), 0.f);                       \
            a1r.w = fmaxf(fmaf(a1r.w, sc.w, sh.w), 0.f);                       \
        }                                                                      \
    } while (0)

#define STSSTAGE(bi) do {                                                      \
        As[bi][akv * 4 + 0][ar]      = a0r.x;                                  \
        As[bi][akv * 4 + 1][ar]      = a0r.y;                                  \
        As[bi][akv * 4 + 2][ar]      = a0r.z;                                  \
        As[bi][akv * 4 + 3][ar]      = a0r.w;                                  \
        As[bi][akv * 4 + 0][ar + 64] = a1r.x;                                  \
        As[bi][akv * 4 + 1][ar + 64] = a1r.y;                                  \
        As[bi][akv * 4 + 2][ar + 64] = a1r.z;                                  \
        As[bi][akv * 4 + 3][ar + 64] = a1r.w;                                  \
        Bs[bi][akv * 4 + 0][ar]      = w0r.x;                                  \
        Bs[bi][akv * 4 + 1][ar]      = w0r.y;                                  \
        Bs[bi][akv * 4 + 2][ar]      = w0r.z;                                  \
        Bs[bi][akv * 4 + 3][ar]      = w0r.w;                                  \
        Bs[bi][akv * 4 + 0][ar + 64] = w1r.x;                                  \
        Bs[bi][akv * 4 + 1][ar + 64] = w1r.y;                                  \
        Bs[bi][akv * 4 + 2][ar + 64] = w1r.z;                                  \
        Bs[bi][akv * 4 + 3][ar + 64] = w1r.w;                                  \
    } while (0)

    LOADSTAGE(0);
    STSSTAGE(0);
    __syncthreads();
    int cur = 0;
    for (int kt = 16; kt < KD; kt += 16) {
        LOADSTAGE(kt);
        compute_tile(As[cur], Bs[cur], cc, tx, ty);
        STSSTAGE(cur ^ 1);
        __syncthreads();
        cur ^= 1;
    }
    compute_tile(As[cur], Bs[cur], cc, tx, ty);
#undef LOADSTAGE
#undef STSSTAGE

    // unpack
    float cr[8][8];
    #pragma unroll
    for (int p = 0; p < 4; p++)
        #pragma unroll
        for (int j = 0; j < 8; j++) {
            float lo, hi; unpack2(cc[p][j], lo, hi);
            cr[2 * p][j] = lo; cr[2 * p + 1][j] = hi;
        }

    float4 bia0 = *(const float4*)(bias + blockIdx.y * 128 + tx * 4);
    float4 bia1 = *(const float4*)(bias + blockIdx.y * 128 + 64 + tx * 4);
    float bj[8] = {bia0.x, bia0.y, bia0.z, bia0.w, bia1.x, bia1.y, bia1.z, bia1.w};

    float ssum[8], ssq[8];
    #pragma unroll
    for (int j = 0; j < 8; j++) { ssum[j] = 0.f; ssq[j] = 0.f; }

    #pragma unroll
    for (int m = 0; m < 8; m++) {
        int grow = blockIdx.x * 128 + ty * 4 + (m & 3) + ((m >= 4) ? 64 : 0);
        float v[8];
        #pragma unroll
        for (int j = 0; j < 8; j++) {
            v[j] = cr[m][j] + bj[j];
            ssum[j] += v[j];
            ssq[j]  += v[j] * v[j];
        }
        float* yp = Y + (size_t)grow * SC + blockIdx.y * 128 + tx * 4;
        *(float4*)(yp)      = make_float4(v[0], v[1], v[2], v[3]);
        *(float4*)(yp + 64) = make_float4(v[4], v[5], v[6], v[7]);
    }

    // per-channel reduction in smem (reuse As), then atomics
    __syncthreads();
    float* red = &As[0][0][0];   // 4224 floats available, need 4096
    #pragma unroll
    for (int j = 0; j < 8; j++) {
        red[tid * 8 + j]        = ssum[j];
        red[2048 + tid * 8 + j] = ssq[j];
    }
    __syncthreads();
    if (tid < 128) {
        int c = tid;
        int half = c >> 6;
        int rr = c & 63;
        int txo = rr >> 2;
        int jj = (rr & 3) + half * 4;
        float s = 0.f, q = 0.f;
        #pragma unroll
        for (int t = 0; t < 16; t++) {
            int t2 = t * 16 + txo;
            s += red[t2 * 8 + jj];
            q += red[2048 + t2 * 8 + jj];
        }
        int cg = blockIdx.y * 128 + c;
        atomicAdd(&stats[cg], s);
        atomicAdd(&stats[SC + cg], q);
    }
}

// ---------------- finalize BN params ----------------
template<bool FIRST>
__global__ void k_fin(const float* __restrict__ g, const float* __restrict__ be) {
    constexpr int C = FIRST ? O1_ : O2_;
    int c = threadIdx.x;
    if (c < C) {
        const float* stats = FIRST ? g_stats1 : g_stats2;
        float mean = stats[c] * (1.0f / ROWS_);
        float var  = stats[C + c] * (1.0f / ROWS_) - mean * mean;
        float rstd = rsqrtf(var + BN_EPS_);
        float s = g[c] * rstd;
        if (FIRST) { g_sc1[c] = s; g_sh1[c] = be[c] - mean * s; }
        else       { g_sc2[c] = s; g_sh2[c] = be[c] - mean * s; }
    }
}

// ---------------- BN2 + ReLU + transpose to output [B][128][N] ----------------
__global__ void k_out(float* __restrict__ out) {
    __shared__ float tile[32][33];
    int b = blockIdx.z;
    int n0 = blockIdx.x * 32, o0 = blockIdx.y * 32;
    int tx = threadIdx.x, ty = threadIdx.y;
    float sc = g_sc2[o0 + tx], sh = g_sh2[o0 + tx];
    const float* src = g_Y2 + ((size_t)(b * N_ + n0)) * O2_ + o0;
    #pragma unroll
    for (int i = ty; i < 32; i += 8) {
        float v = src[(size_t)i * O2_ + tx];
        tile[i][tx] = fmaxf(fmaf(v, sc, sh), 0.f);
    }
    __syncthreads();
    float* dst = out + ((size_t)b * O2_ + o0) * N_ + n0;
    #pragma unroll
    for (int i = ty; i < 32; i += 8)
        dst[(size_t)i * N_ + tx] = tile[tx][i];
}

// ---------------- launch ----------------
extern "C" void kernel_launch(void* const* d_in, const int* in_sizes, int n_in,
                              void* d_out, int out_size) {
    (void)in_sizes; (void)n_in; (void)out_size;
    const float* xyz1    = (const float*)d_in[0];
    const float* xyz2    = (const float*)d_in[1];
    const float* points1 = (const float*)d_in[2];
    const float* points2 = (const float*)d_in[3];
    const float* w1  = (const float*)d_in[4];
    const float* b1  = (const float*)d_in[5];
    const float* g1  = (const float*)d_in[6];
    const float* be1 = (const float*)d_in[7];
    const float* w2  = (const float*)d_in[8];
    const float* b2  = (const float*)d_in[9];
    const float* g2  = (const float*)d_in[10];
    const float* be2 = (const float*)d_in[11];
    float* out = (float*)d_out;

    k_prep<<<64, 256>>>(xyz2);
    k_tr_f2<<<dim3(S_ / 32, D2_ / 32, B_), dim3(32, 8)>>>(points2);
    k_tr_f1<<<dim3(N_ / 32, D1_ / 32, B_), dim3(32, 8)>>>(points1);
    k_nn3<<<dim3(N_ / 256, B_), 256>>>(xyz1);
    k_interp<<<ROWS_, 256>>>();
    k_gemm<true><<<dim3(ROWS_ / 128, 2), 256>>>(w1, b1);
    k_fin<true><<<1, 256>>>(g1, be1);
    k_gemm<false><<<dim3(ROWS_ / 128, 1), 256>>>(w2, b2);
    k_fin<false><<<1, 128>>>(g2, be2);
    k_out<<<dim3(N_ / 32, O2_ / 32, B_), dim3(32, 8)>>>(out);
}

// round 4
// speedup vs baseline: 1.1444x; 1.1444x over previous
#include <cuda_runtime.h>
#include <cuda_bf16.h>
#include <cstdint>

// Problem constants
#define B_    8
#define N_    8192
#define S_    2048
#define D1_   128
#define D2_   256
#define C0_   384          // D1 + D2
#define O1_   256
#define O2_   128
#define ROWS_ 65536        // B_ * N_
#define BN_EPS_ 1e-5f

// ---------------- device scratch (no cudaMalloc allowed) ----------------
__device__ __align__(16) __nv_bfloat16 g_Xh[(size_t)ROWS_ * C0_];  // concat hi
__device__ __align__(16) __nv_bfloat16 g_Xl[(size_t)ROWS_ * C0_];  // concat lo
__device__ __align__(16) float g_Y1[(size_t)ROWS_ * O1_];   // layer1 pre-BN
__device__ __align__(16) float g_Y2[(size_t)ROWS_ * O2_];   // layer2 pre-BN
__device__ __align__(16) float g_f2[(size_t)B_ * S_ * D2_]; // points2 transposed [b][s][d]
__device__ float4 g_p2[B_ * S_];                            // (x,y,z,|p|^2)
__device__ int    g_idx3[ROWS_ * 3];
__device__ float  g_w3 [ROWS_ * 3];
__device__ float  g_stats1[2 * O1_];
__device__ float  g_stats2[2 * O2_];
__device__ float  g_sc1[O1_], g_sh1[O1_];
__device__ float  g_sc2[O2_], g_sh2[O2_];
__device__ __align__(16) __nv_bfloat16 g_w1h[O1_ * C0_], g_w1l[O1_ * C0_];
__device__ __align__(16) __nv_bfloat16 g_w2h[O2_ * O1_], g_w2l[O2_ * O1_];

// ---------------- helpers ----------------
// split fp32 -> bf16 hi + bf16 lo, two lanes packed into one u32 (low half = first elem)
__device__ __forceinline__ void bsplit2(float a, float b, uint32_t& h, uint32_t& l) {
    __nv_bfloat162 hv, lv;
    hv.x = __float2bfloat16_rn(a);
    hv.y = __float2bfloat16_rn(b);
    lv.x = __float2bfloat16_rn(a - __bfloat162float(hv.x));
    lv.y = __float2bfloat16_rn(b - __bfloat162float(hv.y));
    h = *reinterpret_cast<uint32_t*>(&hv);
    l = *reinterpret_cast<uint32_t*>(&lv);
}

// baseline-PTX HMMA: m16n8k16 bf16 x bf16 -> fp32 (sm_80+ feature, compiles for sm_103)
__device__ __forceinline__ void mma16816(float c[4], const uint32_t a[4], const uint32_t b[2]) {
    asm volatile(
        "mma.sync.aligned.m16n8k16.row.col.f32.bf16.bf16.f32 "
        "{%0,%1,%2,%3}, {%4,%5,%6,%7}, {%8,%9}, {%0,%1,%2,%3};"
        : "+f"(c[0]), "+f"(c[1]), "+f"(c[2]), "+f"(c[3])
        : "r"(a[0]), "r"(a[1]), "r"(a[2]), "r"(a[3]), "r"(b[0]), "r"(b[1]));
}

// ---------------- prep: stats zero + xyz2 pack + weight bf16 split ----------------
__global__ void k_pre(const float* __restrict__ xyz2,
                      const float* __restrict__ w1, const float* __restrict__ w2) {
    int t = blockIdx.x * 256 + threadIdx.x;
    if (t < 2 * O1_) g_stats1[t] = 0.f;
    if (t < 2 * O2_) g_stats2[t] = 0.f;
    if (t < B_ * S_) {
        int b = t / S_, s = t % S_;
        const float* p = xyz2 + (size_t)b * 3 * S_;
        float x = p[s], y = p[S_ + s], z = p[2 * S_ + s];
        g_p2[t] = make_float4(x, y, z, x * x + y * y + z * z);
    }
    if (t < O1_ * C0_) {
        float v = w1[t];
        __nv_bfloat16 h = __float2bfloat16_rn(v);
        g_w1h[t] = h;
        g_w1l[t] = __float2bfloat16_rn(v - __bfloat162float(h));
    }
    if (t < O2_ * O1_) {
        float v = w2[t];
        __nv_bfloat16 h = __float2bfloat16_rn(v);
        g_w2h[t] = h;
        g_w2l[t] = __float2bfloat16_rn(v - __bfloat162float(h));
    }
}

// ---------------- transpose points2 [B][D2][S] -> g_f2 [B][S][D2] ----------------
__global__ void k_tr_f2(const float* __restrict__ p2) {
    __shared__ float tile[32][33];
    int b = blockIdx.z;
    int s0 = blockIdx.x * 32, d0 = blockIdx.y * 32;
    int tx = threadIdx.x, ty = threadIdx.y;
    const float* src = p2 + ((size_t)b * D2_ + d0) * S_ + s0;
    #pragma unroll
    for (int i = ty; i < 32; i += 8)
        tile[i][tx] = src[(size_t)i * S_ + tx];
    __syncthreads();
    float* dst = g_f2 + ((size_t)b * S_ + s0) * D2_ + d0;
    #pragma unroll
    for (int i = ty; i < 32; i += 8)
        dst[(size_t)i * D2_ + tx] = tile[tx][i];
}

// ---------------- transpose points1 [B][D1][N] -> split bf16 g_Xh/g_Xl[:, 0:128] ----------------
__global__ void k_tr_f1(const float* __restrict__ p1) {
    __shared__ float tile[32][33];
    int b = blockIdx.z;
    int n0 = blockIdx.x * 32, d0 = blockIdx.y * 32;
    int tx = threadIdx.x, ty = threadIdx.y;
    const float* src = p1 + ((size_t)b * D1_ + d0) * N_ + n0;
    #pragma unroll
    for (int i = ty; i < 32; i += 8)
        tile[i][tx] = src[(size_t)i * N_ + tx];
    __syncthreads();
    size_t base = ((size_t)(b * N_ + n0)) * C0_ + d0;
    #pragma unroll
    for (int i = ty; i < 32; i += 8) {
        float v = tile[tx][i];
        __nv_bfloat16 h = __float2bfloat16_rn(v);
        g_Xh[base + (size_t)i * C0_ + tx] = h;
        g_Xl[base + (size_t)i * C0_ + tx] = __float2bfloat16_rn(v - __bfloat162float(h));
    }
}

// ---------------- 3-NN: 2 queries per thread for ILP ----------------
__global__ __launch_bounds__(128) void k_nn3(const float* __restrict__ xyz1) {
    __shared__ float4 sp[S_];   // 32 KB
    int b = blockIdx.y;
    int n0 = blockIdx.x * 256;
    for (int i = threadIdx.x; i < S_; i += 128) sp[i] = g_p2[b * S_ + i];
    __syncthreads();

    const float* q = xyz1 + (size_t)b * 3 * N_;
    int na = n0 + threadIdx.x, nb = na + 128;
    float xa = q[na], ya = q[N_ + na], za = q[2 * N_ + na];
    float xb = q[nb], yb = q[N_ + nb], zb = q[2 * N_ + nb];
    float axa = -2.f * xa, aya = -2.f * ya, aza = -2.f * za;
    float axb = -2.f * xb, ayb = -2.f * yb, azb = -2.f * zb;

    float a0 = 1e30f, a1 = 1e30f, a2 = 1e30f; int ia0 = 0, ia1 = 0, ia2 = 0;
    float b0 = 1e30f, b1 = 1e30f, b2 = 1e30f; int ib0 = 0, ib1 = 0, ib2 = 0;
    #pragma unroll 4
    for (int s = 0; s < S_; s++) {
        float4 p = sp[s];
        float da = fmaf(p.x, axa, fmaf(p.y, aya, fmaf(p.z, aza, p.w)));
        float db = fmaf(p.x, axb, fmaf(p.y, ayb, fmaf(p.z, azb, p.w)));
        if (da < a2) {
            if (da < a1) {
                a2 = a1; ia2 = ia1;
                if (da < a0) { a1 = a0; ia1 = ia0; a0 = da; ia0 = s; }
                else         { a1 = da; ia1 = s; }
            } else { a2 = da; ia2 = s; }
        }
        if (db < b2) {
            if (db < b1) {
                b2 = b1; ib2 = ib1;
                if (db < b0) { b1 = b0; ib1 = ib0; b0 = db; ib0 = s; }
                else         { b1 = db; ib1 = s; }
            } else { b2 = db; ib2 = s; }
        }
    }
    {
        float r1 = xa * xa + ya * ya + za * za;
        float t0 = fmaxf(a0 + r1, 1e-10f), t1 = fmaxf(a1 + r1, 1e-10f), t2 = fmaxf(a2 + r1, 1e-10f);
        float w0 = 1.f / t0, w1 = 1.f / t1, w2 = 1.f / t2;
        float inv = 1.f / (w0 + w1 + w2);
        size_t row = (size_t)b * N_ + na;
        g_idx3[row * 3 + 0] = ia0; g_idx3[row * 3 + 1] = ia1; g_idx3[row * 3 + 2] = ia2;
        g_w3 [row * 3 + 0] = w0 * inv; g_w3[row * 3 + 1] = w1 * inv; g_w3[row * 3 + 2] = w2 * inv;
    }
    {
        float r1 = xb * xb + yb * yb + zb * zb;
        float t0 = fmaxf(b0 + r1, 1e-10f), t1 = fmaxf(b1 + r1, 1e-10f), t2 = fmaxf(b2 + r1, 1e-10f);
        float w0 = 1.f / t0, w1 = 1.f / t1, w2 = 1.f / t2;
        float inv = 1.f / (w0 + w1 + w2);
        size_t row = (size_t)b * N_ + nb;
        g_idx3[row * 3 + 0] = ib0; g_idx3[row * 3 + 1] = ib1; g_idx3[row * 3 + 2] = ib2;
        g_w3 [row * 3 + 0] = w0 * inv; g_w3[row * 3 + 1] = w1 * inv; g_w3[row * 3 + 2] = w2 * inv;
    }
}

// ---------------- gather + interpolate -> split bf16 g_Xh/g_Xl[:, 128:384] ----------------
__global__ void k_interp() {
    unsigned row = blockIdx.x;
    int d = threadIdx.x;
    int b = row / N_;
    int  i0 = g_idx3[(size_t)row * 3 + 0];
    int  i1 = g_idx3[(size_t)row * 3 + 1];
    int  i2 = g_idx3[(size_t)row * 3 + 2];
    float w0 = g_w3[(size_t)row * 3 + 0];
    float w1 = g_w3[(size_t)row * 3 + 1];
    float w2 = g_w3[(size_t)row * 3 + 2];
    const float* f = g_f2 + (size_t)b * S_ * D2_;
    float v = w0 * f[(size_t)i0 * D2_ + d]
            + w1 * f[(size_t)i1 * D2_ + d]
            + w2 * f[(size_t)i2 * D2_ + d];
    size_t o = (size_t)row * C0_ + D1_ + d;
    __nv_bfloat16 h = __float2bfloat16_rn(v);
    g_Xh[o] = h;
    g_Xl[o] = __float2bfloat16_rn(v - __bfloat162float(h));
}

// ---------------- HMMA bf16-split GEMM: Y = A @ W^T + bias ----------------
// CTA tile 128x128, 8 warps of 64x32, k-chunk 32, double-buffered smem.
// smem tile layout: [128 rows][40 bf16] (pad 40 => conflict-free 8x4 frag pattern)
#define TILE_STRIDE 40
#define OFF_AH 0
#define OFF_AL 10240
#define OFF_BH 20480
#define OFF_BL 30720
#define STG_BYTES 40960

template<bool FIRST>
__global__ __launch_bounds__(256, 1) void k_gemm_mma(const float* __restrict__ bias) {
    constexpr int KD = FIRST ? C0_ : O1_;
    constexpr int NO = FIRST ? O1_ : O2_;
    constexpr int NCH = KD / 32;

    const __nv_bfloat16* __restrict__ Wh = FIRST ? g_w1h : g_w2h;
    const __nv_bfloat16* __restrict__ Wl = FIRST ? g_w1l : g_w2l;
    float* __restrict__ Y = FIRST ? g_Y1 : g_Y2;

    extern __shared__ char sm[];

    const int tid = threadIdx.x;
    const int lane = tid & 31, wid = tid >> 5;
    const int g = lane >> 2, tig = lane & 3;
    const int wm = wid & 1, wn = wid >> 1;       // 2 x 4 warp grid
    const int r0 = blockIdx.x * 128;
    const int n0 = blockIdx.y * 128;

    float acc[4][4][4];
    #pragma unroll
    for (int m = 0; m < 4; m++)
        #pragma unroll
        for (int n = 0; n < 4; n++)
            #pragma unroll
            for (int j = 0; j < 4; j++) acc[m][n][j] = 0.f;

    // ---- per-thread LDG indices
    const int arow = tid >> 2, aseg = (tid & 3) * 8;           // GEMM1 A + both B: 2 iters of 256
    const int frow = tid >> 1, fhalf = (tid & 1) * 16;         // GEMM2 A: 16 floats/thread

    uint4 rAh[2], rAl[2], rBh[2], rBl[2];

#define LDG_CHUNK(kc) do {                                                        \
        if (FIRST) {                                                              \
            _Pragma("unroll")                                                     \
            for (int i = 0; i < 2; i++) {                                         \
                int row = arow + i * 64;                                          \
                rAh[i] = *(const uint4*)&g_Xh[(size_t)(r0 + row) * C0_ + (kc) + aseg]; \
                rAl[i] = *(const uint4*)&g_Xl[(size_t)(r0 + row) * C0_ + (kc) + aseg]; \
                rBh[i] = *(const uint4*)&Wh[(size_t)(n0 + row) * KD + (kc) + aseg];    \
                rBl[i] = *(const uint4*)&Wl[(size_t)(n0 + row) * KD + (kc) + aseg];    \
            }                                                                     \
        } else {                                                                  \
            /* A = Y1 fp32 with BN1 + ReLU, then split */                         \
            const float* ap = g_Y1 + (size_t)(r0 + frow) * O1_ + (kc) + fhalf;    \
            const float* scp = g_sc1 + (kc) + fhalf;                              \
            const float* shp = g_sh1 + (kc) + fhalf;                              \
            _Pragma("unroll")                                                     \
            for (int i = 0; i < 2; i++) {                                         \
                float4 u = *(const float4*)(ap + i * 8);                          \
                float4 v = *(const float4*)(ap + i * 8 + 4);                      \
                float4 scu = *(const float4*)(scp + i * 8);                       \
                float4 shu = *(const float4*)(shp + i * 8);                       \
                float4 scv = *(const float4*)(scp + i * 8 + 4);                   \
                float4 shv = *(const float4*)(shp + i * 8 + 4);                   \
                u.x = fmaxf(fmaf(u.x, scu.x, shu.x), 0.f);                        \
                u.y = fmaxf(fmaf(u.y, scu.y, shu.y), 0.f);                        \
                u.z = fmaxf(fmaf(u.z, scu.z, shu.z), 0.f);                        \
                u.w = fmaxf(fmaf(u.w, scu.w, shu.w), 0.f);                        \
                v.x = fmaxf(fmaf(v.x, scv.x, shv.x), 0.f);                        \
                v.y = fmaxf(fmaf(v.y, scv.y, shv.y), 0.f);                        \
                v.z = fmaxf(fmaf(v.z, scv.z, shv.z), 0.f);                        \
                v.w = fmaxf(fmaf(v.w, scv.w, shv.w), 0.f);                        \
                bsplit2(u.x, u.y, rAh[i].x, rAl[i].x);                            \
                bsplit2(u.z, u.w, rAh[i].y, rAl[i].y);                            \
                bsplit2(v.x, v.y, rAh[i].z, rAl[i].z);                            \
                bsplit2(v.z, v.w, rAh[i].w, rAl[i].w);                            \
            }                                                                     \
            _Pragma("unroll")                                                     \
            for (int i = 0; i < 2; i++) {                                         \
                int row = arow + i * 64;                                          \
                rBh[i] = *(const uint4*)&Wh[(size_t)(n0 + row) * KD + (kc) + aseg];    \
                rBl[i] = *(const uint4*)&Wl[(size_t)(n0 + row) * KD + (kc) + aseg];    \
            }                                                                     \
        }                                                                         \
    } while (0)

#define STS_CHUNK(buf) do {                                                       \
        char* bp = sm + (buf) * STG_BYTES;                                        \
        if (FIRST) {                                                              \
            _Pragma("unroll")                                                     \
            for (int i = 0; i < 2; i++) {                                         \
                int row = arow + i * 64;                                          \
                int off = (row * TILE_STRIDE + aseg) * 2;                         \
                *(uint4*)(bp + OFF_AH + off) = rAh[i];                            \
                *(uint4*)(bp + OFF_AL + off) = rAl[i];                            \
                *(uint4*)(bp + OFF_BH + off) = rBh[i];                            \
                *(uint4*)(bp + OFF_BL + off) = rBl[i];                            \
            }                                                                     \
        } else {                                                                  \
            int offa = (frow * TILE_STRIDE + fhalf) * 2;                          \
            *(uint4*)(bp + OFF_AH + offa)      = rAh[0];                          \
            *(uint4*)(bp + OFF_AH + offa + 16) = rAh[1];                          \
            *(uint4*)(bp + OFF_AL + offa)      = rAl[0];                          \
            *(uint4*)(bp + OFF_AL + offa + 16) = rAl[1];                          \
            _Pragma("unroll")                                                     \
            for (int i = 0; i < 2; i++) {                                         \
                int row = arow + i * 64;                                          \
                int off = (row * TILE_STRIDE + aseg) * 2;                         \
                *(uint4*)(bp + OFF_BH + off) = rBh[i];                            \
                *(uint4*)(bp + OFF_BL + off) = rBl[i];                            \
            }                                                                     \
        }                                                                         \
    } while (0)

    LDG_CHUNK(0);
    STS_CHUNK(0);
    __syncthreads();

    for (int ch = 0; ch < NCH; ch++) {
        if (ch + 1 < NCH) LDG_CHUNK((ch + 1) * 32);

        // ---- compute on buffer ch&1
        {
            const char* bp = sm + (ch & 1) * STG_BYTES;
            const uint32_t* A32h = (const uint32_t*)(bp + OFF_AH);
            const uint32_t* A32l = (const uint32_t*)(bp + OFF_AL);
            const uint32_t* B32h = (const uint32_t*)(bp + OFF_BH);
            const uint32_t* B32l = (const uint32_t*)(bp + OFF_BL);
            #pragma unroll
            for (int ko = 0; ko < 2; ko++) {
                const int cb = ko * 8 + tig;   // u32 col
                uint32_t ah[4][4], al[4][4], bh[4][2], bl[4][2];
                #pragma unroll
                for (int mt = 0; mt < 4; mt++) {
                    int rr = (wm * 64 + mt * 16 + g) * (TILE_STRIDE / 2) + cb;
                    ah[mt][0] = A32h[rr];
                    ah[mt][1] = A32h[rr + 8 * (TILE_STRIDE / 2)];
                    ah[mt][2] = A32h[rr + 4];
                    ah[mt][3] = A32h[rr + 8 * (TILE_STRIDE / 2) + 4];
                    al[mt][0] = A32l[rr];
                    al[mt][1] = A32l[rr + 8 * (TILE_STRIDE / 2)];
                    al[mt][2] = A32l[rr + 4];
                    al[mt][3] = A32l[rr + 8 * (TILE_STRIDE / 2) + 4];
                }
                #pragma unroll
                for (int nt = 0; nt < 4; nt++) {
                    int rn = (wn * 32 + nt * 8 + g) * (TILE_STRIDE / 2) + cb;
                    bh[nt][0] = B32h[rn];
                    bh[nt][1] = B32h[rn + 4];
                    bl[nt][0] = B32l[rn];
                    bl[nt][1] = B32l[rn + 4];
                }
                #pragma unroll
                for (int mt = 0; mt < 4; mt++)
                    #pragma unroll
                    for (int nt = 0; nt < 4; nt++) {
                        mma16816(acc[mt][nt], ah[mt], bh[nt]);
                        mma16816(acc[mt][nt], ah[mt], bl[nt]);
                        mma16816(acc[mt][nt], al[mt], bh[nt]);
                    }
            }
        }

        if (ch + 1 < NCH) STS_CHUNK((ch + 1) & 1);
        __syncthreads();
    }
#undef LDG_CHUNK
#undef STS_CHUNK

    // ---- epilogue: + bias, store Y row-major fp32
    #pragma unroll
    for (int mt = 0; mt < 4; mt++) {
        int row = r0 + wm * 64 + mt * 16 + g;
        #pragma unroll
        for (int nt = 0; nt < 4; nt++) {
            int col = n0 + wn * 32 + nt * 8 + 2 * tig;
            float bv0 = __ldg(bias + col), bv1 = __ldg(bias + col + 1);
            float2 o0 = make_float2(acc[mt][nt][0] + bv0, acc[mt][nt][1] + bv1);
            float2 o1 = make_float2(acc[mt][nt][2] + bv0, acc[mt][nt][3] + bv1);
            *(float2*)&Y[(size_t)row * NO + col]       = o0;
            *(float2*)&Y[(size_t)(row + 8) * NO + col] = o1;
        }
    }
}

// ---------------- per-channel sum / sumsq over rows (device globals only!) ----------------
template<bool FIRST>
__global__ void k_stats() {
    constexpr int C = FIRST ? O1_ : O2_;
    const float* __restrict__ Y = FIRST ? g_Y1 : g_Y2;
    float* __restrict__ stats   = FIRST ? g_stats1 : g_stats2;
    int c = threadIdx.x;                      // blockDim.x == C
    size_t r0 = (size_t)blockIdx.x * 256;
    const float* p = Y + r0 * C + c;
    float s = 0.f, q = 0.f;
    #pragma unroll 8
    for (int i = 0; i < 256; i++) {
        float v = p[(size_t)i * C];
        s += v; q += v * v;
    }
    atomicAdd(&stats[c], s);
    atomicAdd(&stats[C + c], q);
}

// ---------------- finalize BN params ----------------
template<bool FIRST>
__global__ void k_fin(const float* __restrict__ g, const float* __restrict__ be) {
    constexpr int C = FIRST ? O1_ : O2_;
    int c = threadIdx.x;
    if (c < C) {
        const float* stats = FIRST ? g_stats1 : g_stats2;
        float mean = stats[c] * (1.0f / ROWS_);
        float var  = stats[C + c] * (1.0f / ROWS_) - mean * mean;
        float rstd = rsqrtf(var + BN_EPS_);
        float s = g[c] * rstd;
        if (FIRST) { g_sc1[c] = s; g_sh1[c] = be[c] - mean * s; }
        else       { g_sc2[c] = s; g_sh2[c] = be[c] - mean * s; }
    }
}

// ---------------- BN2 + ReLU + transpose to output [B][128][N] ----------------
__global__ void k_out(float* __restrict__ out) {
    __shared__ float tile[32][33];
    int b = blockIdx.z;
    int n0 = blockIdx.x * 32, o0 = blockIdx.y * 32;
    int tx = threadIdx.x, ty = threadIdx.y;
    float sc = g_sc2[o0 + tx], sh = g_sh2[o0 + tx];
    const float* src = g_Y2 + ((size_t)(b * N_ + n0)) * O2_ + o0;
    #pragma unroll
    for (int i = ty; i < 32; i += 8) {
        float v = src[(size_t)i * O2_ + tx];
        tile[i][tx] = fmaxf(fmaf(v, sc, sh), 0.f);
    }
    __syncthreads();
    float* dst = out + ((size_t)b * O2_ + o0) * N_ + n0;
    #pragma unroll
    for (int i = ty; i < 32; i += 8)
        dst[(size_t)i * N_ + tx] = tile[tx][i];
}

// ---------------- launch ----------------
extern "C" void kernel_launch(void* const* d_in, const int* in_sizes, int n_in,
                              void* d_out, int out_size) {
    (void)in_sizes; (void)n_in; (void)out_size;
    const float* xyz1    = (const float*)d_in[0];
    const float* xyz2    = (const float*)d_in[1];
    const float* points1 = (const float*)d_in[2];
    const float* points2 = (const float*)d_in[3];
    const float* w1  = (const float*)d_in[4];
    const float* b1  = (const float*)d_in[5];
    const float* g1  = (const float*)d_in[6];
    const float* be1 = (const float*)d_in[7];
    const float* w2  = (const float*)d_in[8];
    const float* b2  = (const float*)d_in[9];
    const float* g2  = (const float*)d_in[10];
    const float* be2 = (const float*)d_in[11];
    float* out = (float*)d_out;

    const int SMEM = 2 * STG_BYTES;   // 81920
    cudaFuncSetAttribute(k_gemm_mma<true>,  cudaFuncAttributeMaxDynamicSharedMemorySize, SMEM);
    cudaFuncSetAttribute(k_gemm_mma<false>, cudaFuncAttributeMaxDynamicSharedMemorySize, SMEM);

    k_pre<<<384, 256>>>(xyz2, w1, w2);                                   // launch 0
    k_tr_f2<<<dim3(S_ / 32, D2_ / 32, B_), dim3(32, 8)>>>(points2);      // launch 1
    k_tr_f1<<<dim3(N_ / 32, D1_ / 32, B_), dim3(32, 8)>>>(points1);      // launch 2
    k_nn3<<<dim3(N_ / 256, B_), 128>>>(xyz1);                            // launch 3
    k_interp<<<ROWS_, 256>>>();                                          // launch 4
    k_gemm_mma<true><<<dim3(ROWS_ / 128, 2), 256, SMEM>>>(b1);           // launch 5 (ncu slot)
    k_stats<true><<<ROWS_ / 256, O1_>>>();
    k_fin<true><<<1, 256>>>(g1, be1);
    k_gemm_mma<false><<<dim3(ROWS_ / 128, 1), 256, SMEM>>>(b2);
    k_stats<false><<<ROWS_ / 256, O2_>>>();
    k_fin<false><<<1, 128>>>(g2, be2);
    k_out<<<dim3(N_ / 32, O2_ / 32, B_), dim3(32, 8)>>>(out);
}

// round 5
// speedup vs baseline: 1.3549x; 1.1839x over previous
#include <cuda_runtime.h>
#include <cuda_bf16.h>
#include <cstdint>

// Problem constants
#define B_    8
#define N_    8192
#define S_    2048
#define D1_   128
#define D2_   256
#define C0_   384          // D1 + D2
#define O1_   256
#define O2_   128
#define ROWS_ 65536        // B_ * N_
#define BN_EPS_ 1e-5f
#define NPART 4
#define SPART (S_ / NPART)   // 512

// ---------------- device scratch (no cudaMalloc allowed) ----------------
__device__ __align__(16) __nv_bfloat16 g_Xh[(size_t)ROWS_ * C0_];  // concat hi
__device__ __align__(16) __nv_bfloat16 g_Xl[(size_t)ROWS_ * C0_];  // concat lo
__device__ __align__(16) float g_Y1[(size_t)ROWS_ * O1_];   // layer1 pre-BN
__device__ __align__(16) float g_Y2[(size_t)ROWS_ * O2_];   // layer2 pre-BN
__device__ __align__(16) float g_f2[(size_t)B_ * S_ * D2_]; // points2 transposed [b][s][d]
__device__ float4 g_p2[B_ * S_];                            // (x,y,z,|p|^2)
__device__ __align__(16) float g_cd[(size_t)ROWS_ * 12];    // split-NN candidate dists
__device__ __align__(16) int   g_ci[(size_t)ROWS_ * 12];    // split-NN candidate idx
__device__ int    g_idx3[ROWS_ * 3];
__device__ float  g_w3 [ROWS_ * 3];
__device__ float  g_stats1[2 * O1_];
__device__ float  g_stats2[2 * O2_];
__device__ float  g_sc1[O1_], g_sh1[O1_];
__device__ float  g_sc2[O2_], g_sh2[O2_];
__device__ __align__(16) __nv_bfloat16 g_w1h[O1_ * C0_], g_w1l[O1_ * C0_];
__device__ __align__(16) __nv_bfloat16 g_w2h[O2_ * O1_], g_w2l[O2_ * O1_];

// ---------------- helpers ----------------
// split fp32 -> bf16 hi + bf16 lo, two lanes packed into one u32 (low half = first elem)
__device__ __forceinline__ void bsplit2(float a, float b, uint32_t& h, uint32_t& l) {
    __nv_bfloat162 hv, lv;
    hv.x = __float2bfloat16_rn(a);
    hv.y = __float2bfloat16_rn(b);
    lv.x = __float2bfloat16_rn(a - __bfloat162float(hv.x));
    lv.y = __float2bfloat16_rn(b - __bfloat162float(hv.y));
    h = *reinterpret_cast<uint32_t*>(&hv);
    l = *reinterpret_cast<uint32_t*>(&lv);
}

// baseline-PTX HMMA: m16n8k16 bf16 x bf16 -> fp32 (sm_80+ feature, compiles for sm_103)
__device__ __forceinline__ void mma16816(float c[4], const uint32_t a[4], const uint32_t b[2]) {
    asm volatile(
        "mma.sync.aligned.m16n8k16.row.col.f32.bf16.bf16.f32 "
        "{%0,%1,%2,%3}, {%4,%5,%6,%7}, {%8,%9}, {%0,%1,%2,%3};"
        : "+f"(c[0]), "+f"(c[1]), "+f"(c[2]), "+f"(c[3])
        : "r"(a[0]), "r"(a[1]), "r"(a[2]), "r"(a[3]), "r"(b[0]), "r"(b[1]));
}

// ---------------- prep: stats zero + xyz2 pack + weight bf16 split ----------------
__global__ void k_pre(const float* __restrict__ xyz2,
                      const float* __restrict__ w1, const float* __restrict__ w2) {
    int t = blockIdx.x * 256 + threadIdx.x;
    if (t < 2 * O1_) g_stats1[t] = 0.f;
    if (t < 2 * O2_) g_stats2[t] = 0.f;
    if (t < B_ * S_) {
        int b = t / S_, s = t % S_;
        const float* p = xyz2 + (size_t)b * 3 * S_;
        float x = p[s], y = p[S_ + s], z = p[2 * S_ + s];
        g_p2[t] = make_float4(x, y, z, x * x + y * y + z * z);
    }
    if (t < O1_ * C0_) {
        float v = w1[t];
        __nv_bfloat16 h = __float2bfloat16_rn(v);
        g_w1h[t] = h;
        g_w1l[t] = __float2bfloat16_rn(v - __bfloat162float(h));
    }
    if (t < O2_ * O1_) {
        float v = w2[t];
        __nv_bfloat16 h = __float2bfloat16_rn(v);
        g_w2h[t] = h;
        g_w2l[t] = __float2bfloat16_rn(v - __bfloat162float(h));
    }
}

// ---------------- transpose points2 [B][D2][S] -> g_f2 [B][S][D2] ----------------
__global__ void k_tr_f2(const float* __restrict__ p2) {
    __shared__ float tile[32][33];
    int b = blockIdx.z;
    int s0 = blockIdx.x * 32, d0 = blockIdx.y * 32;
    int tx = threadIdx.x, ty = threadIdx.y;
    const float* src = p2 + ((size_t)b * D2_ + d0) * S_ + s0;
    #pragma unroll
    for (int i = ty; i < 32; i += 8)
        tile[i][tx] = src[(size_t)i * S_ + tx];
    __syncthreads();
    float* dst = g_f2 + ((size_t)b * S_ + s0) * D2_ + d0;
    #pragma unroll
    for (int i = ty; i < 32; i += 8)
        dst[(size_t)i * D2_ + tx] = tile[tx][i];
}

// ---------------- transpose points1 [B][D1][N] -> split bf16 g_Xh/g_Xl[:, 0:128] ----------------
__global__ void k_tr_f1(const float* __restrict__ p1) {
    __shared__ float tile[32][33];
    int b = blockIdx.z;
    int n0 = blockIdx.x * 32, d0 = blockIdx.y * 32;
    int tx = threadIdx.x, ty = threadIdx.y;
    const float* src = p1 + ((size_t)b * D1_ + d0) * N_ + n0;
    #pragma unroll
    for (int i = ty; i < 32; i += 8)
        tile[i][tx] = src[(size_t)i * N_ + tx];
    __syncthreads();
    size_t base = ((size_t)(b * N_ + n0)) * C0_ + d0;
    #pragma unroll
    for (int i = ty; i < 32; i += 8) {
        float v = tile[tx][i];
        __nv_bfloat16 h = __float2bfloat16_rn(v);
        g_Xh[base + (size_t)i * C0_ + tx] = h;
        g_Xl[base + (size_t)i * C0_ + tx] = __float2bfloat16_rn(v - __bfloat162float(h));
    }
}

// ---------------- 3-NN split over S: each block scans SPART refs for 256 queries ----------------
__global__ __launch_bounds__(256) void k_nn3p(const float* __restrict__ xyz1) {
    __shared__ float4 sp[SPART];   // 8 KB
    int b = blockIdx.y, part = blockIdx.z;
    int n = blockIdx.x * 256 + threadIdx.x;
    for (int i = threadIdx.x; i < SPART; i += 256)
        sp[i] = g_p2[b * S_ + part * SPART + i];
    __syncthreads();

    const float* q = xyz1 + (size_t)b * 3 * N_;
    float x = q[n], y = q[N_ + n], z = q[2 * N_ + n];
    float nx = -2.f * x, ny = -2.f * y, nz = -2.f * z;

    float d0 = 1e30f, d1 = 1e30f, d2 = 1e30f;
    int i0 = 0, i1 = 0, i2 = 0;
    #pragma unroll 4
    for (int s = 0; s < SPART; s++) {
        float4 p = sp[s];
        float d = fmaf(p.x, nx, fmaf(p.y, ny, fmaf(p.z, nz, p.w)));
        if (d < d2) {
            if (d < d1) {
                d2 = d1; i2 = i1;
                if (d < d0) { d1 = d0; i1 = i0; d0 = d; i0 = s; }
                else        { d1 = d;  i1 = s; }
            } else { d2 = d; i2 = s; }
        }
    }
    size_t row = (size_t)b * N_ + n;
    size_t o = row * 12 + part * 3;
    int base = part * SPART;
    g_cd[o + 0] = d0; g_cd[o + 1] = d1; g_cd[o + 2] = d2;
    g_ci[o + 0] = base + i0; g_ci[o + 1] = base + i1; g_ci[o + 2] = base + i2;
}

// ---------------- merge 12 candidates -> final top-3 + weights ----------------
__global__ void k_merge(const float* __restrict__ xyz1) {
    int t = blockIdx.x * 256 + threadIdx.x;   // row 0..65535
    int b = t / N_, n = t % N_;
    float d0 = 1e30f, d1 = 1e30f, d2 = 1e30f;
    int i0 = 0, i1 = 0, i2 = 0;
    const float* cd = g_cd + (size_t)t * 12;
    const int*   ci = g_ci + (size_t)t * 12;
    #pragma unroll
    for (int j = 0; j < 12; j++) {
        float d = cd[j]; int ix = ci[j];
        if (d < d2) {
            if (d < d1) {
                d2 = d1; i2 = i1;
                if (d < d0) { d1 = d0; i1 = i0; d0 = d; i0 = ix; }
                else        { d1 = d;  i1 = ix; }
            } else { d2 = d; i2 = ix; }
        }
    }
    const float* q = xyz1 + (size_t)b * 3 * N_;
    float x = q[n], y = q[N_ + n], z = q[2 * N_ + n];
    float r1 = x * x + y * y + z * z;
    float t0 = fmaxf(d0 + r1, 1e-10f);
    float t1 = fmaxf(d1 + r1, 1e-10f);
    float t2 = fmaxf(d2 + r1, 1e-10f);
    float w0 = 1.f / t0, w1 = 1.f / t1, w2 = 1.f / t2;
    float inv = 1.f / (w0 + w1 + w2);
    g_idx3[(size_t)t * 3 + 0] = i0; g_idx3[(size_t)t * 3 + 1] = i1; g_idx3[(size_t)t * 3 + 2] = i2;
    g_w3 [(size_t)t * 3 + 0] = w0 * inv;
    g_w3 [(size_t)t * 3 + 1] = w1 * inv;
    g_w3 [(size_t)t * 3 + 2] = w2 * inv;
}

// ---------------- gather + interpolate (float4) -> split bf16 g_Xh/g_Xl[:, 128:384] ----------------
__global__ __launch_bounds__(256) void k_interp() {
    int t = threadIdx.x;
    int lr = t >> 6, ln = t & 63;              // 4 rows x 64 lanes of float4
    unsigned row = blockIdx.x * 4 + lr;
    int b = row / N_;
    int  i0 = g_idx3[(size_t)row * 3 + 0];
    int  i1 = g_idx3[(size_t)row * 3 + 1];
    int  i2 = g_idx3[(size_t)row * 3 + 2];
    float w0 = g_w3[(size_t)row * 3 + 0];
    float w1 = g_w3[(size_t)row * 3 + 1];
    float w2 = g_w3[(size_t)row * 3 + 2];
    const float4* f = (const float4*)(g_f2 + (size_t)b * S_ * D2_);
    float4 v0 = f[(size_t)i0 * 64 + ln];
    float4 v1 = f[(size_t)i1 * 64 + ln];
    float4 v2 = f[(size_t)i2 * 64 + ln];
    float4 v;
    v.x = w0 * v0.x + w1 * v1.x + w2 * v2.x;
    v.y = w0 * v0.y + w1 * v1.y + w2 * v2.y;
    v.z = w0 * v0.z + w1 * v1.z + w2 * v2.z;
    v.w = w0 * v0.w + w1 * v1.w + w2 * v2.w;
    uint2 hq, lq;
    bsplit2(v.x, v.y, hq.x, lq.x);
    bsplit2(v.z, v.w, hq.y, lq.y);
    size_t o = (size_t)row * C0_ + D1_ + ln * 4;
    *(uint2*)&g_Xh[o] = hq;
    *(uint2*)&g_Xl[o] = lq;
}

// ---------------- HMMA bf16-split GEMM: Y = A @ W^T + bias ----------------
// CTA tile 128x128, 8 warps of 64x32, k-chunk 32, double-buffered smem.
// smem tile layout: [128 rows][40 bf16] (pad 40 => conflict-free 8x4 frag pattern)
#define TILE_STRIDE 40
#define OFF_AH 0
#define OFF_AL 10240
#define OFF_BH 20480
#define OFF_BL 30720
#define STG_BYTES 40960

template<bool FIRST>
__global__ __launch_bounds__(256, 1) void k_gemm_mma(const float* __restrict__ bias) {
    constexpr int KD = FIRST ? C0_ : O1_;
    constexpr int NO = FIRST ? O1_ : O2_;
    constexpr int NCH = KD / 32;

    const __nv_bfloat16* __restrict__ Wh = FIRST ? g_w1h : g_w2h;
    const __nv_bfloat16* __restrict__ Wl = FIRST ? g_w1l : g_w2l;
    float* __restrict__ Y = FIRST ? g_Y1 : g_Y2;

    extern __shared__ char sm[];

    const int tid = threadIdx.x;
    const int lane = tid & 31, wid = tid >> 5;
    const int g = lane >> 2, tig = lane & 3;
    const int wm = wid & 1, wn = wid >> 1;       // 2 x 4 warp grid
    const int r0 = blockIdx.x * 128;
    const int n0 = blockIdx.y * 128;

    float acc[4][4][4];
    #pragma unroll
    for (int m = 0; m < 4; m++)
        #pragma unroll
        for (int n = 0; n < 4; n++)
            #pragma unroll
            for (int j = 0; j < 4; j++) acc[m][n][j] = 0.f;

    // ---- per-thread LDG indices
    const int arow = tid >> 2, aseg = (tid & 3) * 8;           // GEMM1 A + both B: 2 iters of 256
    const int frow = tid >> 1, fhalf = (tid & 1) * 16;         // GEMM2 A: 16 floats/thread

    uint4 rAh[2], rAl[2], rBh[2], rBl[2];

#define LDG_CHUNK(kc) do {                                                        \
        if (FIRST) {                                                              \
            _Pragma("unroll")                                                     \
            for (int i = 0; i < 2; i++) {                                         \
                int row = arow + i * 64;                                          \
                rAh[i] = *(const uint4*)&g_Xh[(size_t)(r0 + row) * C0_ + (kc) + aseg]; \
                rAl[i] = *(const uint4*)&g_Xl[(size_t)(r0 + row) * C0_ + (kc) + aseg]; \
                rBh[i] = *(const uint4*)&Wh[(size_t)(n0 + row) * KD + (kc) + aseg];    \
                rBl[i] = *(const uint4*)&Wl[(size_t)(n0 + row) * KD + (kc) + aseg];    \
            }                                                                     \
        } else {                                                                  \
            /* A = Y1 fp32 with BN1 + ReLU, then split */                         \
            const float* ap = g_Y1 + (size_t)(r0 + frow) * O1_ + (kc) + fhalf;    \
            const float* scp = g_sc1 + (kc) + fhalf;                              \
            const float* shp = g_sh1 + (kc) + fhalf;                              \
            _Pragma("unroll")                                                     \
            for (int i = 0; i < 2; i++) {                                         \
                float4 u = *(const float4*)(ap + i * 8);                          \
                float4 v = *(const float4*)(ap + i * 8 + 4);                      \
                float4 scu = *(const float4*)(scp + i * 8);                       \
                float4 shu = *(const float4*)(shp + i * 8);                       \
                float4 scv = *(const float4*)(scp + i * 8 + 4);                   \
                float4 shv = *(const float4*)(shp + i * 8 + 4);                   \
                u.x = fmaxf(fmaf(u.x, scu.x, shu.x), 0.f);                        \
                u.y = fmaxf(fmaf(u.y, scu.y, shu.y), 0.f);                        \
                u.z = fmaxf(fmaf(u.z, scu.z, shu.z), 0.f);                        \
                u.w = fmaxf(fmaf(u.w, scu.w, shu.w), 0.f);                        \
                v.x = fmaxf(fmaf(v.x, scv.x, shv.x), 0.f);                        \
                v.y = fmaxf(fmaf(v.y, scv.y, shv.y), 0.f);                        \
                v.z = fmaxf(fmaf(v.z, scv.z, shv.z), 0.f);                        \
                v.w = fmaxf(fmaf(v.w, scv.w, shv.w), 0.f);                        \
                bsplit2(u.x, u.y, rAh[i].x, rAl[i].x);                            \
                bsplit2(u.z, u.w, rAh[i].y, rAl[i].y);                            \
                bsplit2(v.x, v.y, rAh[i].z, rAl[i].z);                            \
                bsplit2(v.z, v.w, rAh[i].w, rAl[i].w);                            \
            }                                                                     \
            _Pragma("unroll")                                                     \
            for (int i = 0; i < 2; i++) {                                         \
                int row = arow + i * 64;                                          \
                rBh[i] = *(const uint4*)&Wh[(size_t)(n0 + row) * KD + (kc) + aseg];    \
                rBl[i] = *(const uint4*)&Wl[(size_t)(n0 + row) * KD + (kc) + aseg];    \
            }                                                                     \
        }                                                                         \
    } while (0)

#define STS_CHUNK(buf) do {                                                       \
        char* bp = sm + (buf) * STG_BYTES;                                        \
        if (FIRST) {                                                              \
            _Pragma("unroll")                                                     \
            for (int i = 0; i < 2; i++) {                                         \
                int row = arow + i * 64;                                          \
                int off = (row * TILE_STRIDE + aseg) * 2;                         \
                *(uint4*)(bp + OFF_AH + off) = rAh[i];                            \
                *(uint4*)(bp + OFF_AL + off) = rAl[i];                            \
                *(uint4*)(bp + OFF_BH + off) = rBh[i];                            \
                *(uint4*)(bp + OFF_BL + off) = rBl[i];                            \
            }                                                                     \
        } else {                                                                  \
            int offa = (frow * TILE_STRIDE + fhalf) * 2;                          \
            *(uint4*)(bp + OFF_AH + offa)      = rAh[0];                          \
            *(uint4*)(bp + OFF_AH + offa + 16) = rAh[1];                          \
            *(uint4*)(bp + OFF_AL + offa)      = rAl[0];                          \
            *(uint4*)(bp + OFF_AL + offa + 16) = rAl[1];                          \
            _Pragma("unroll")                                                     \
            for (int i = 0; i < 2; i++) {                                         \
                int row = arow + i * 64;                                          \
                int off = (row * TILE_STRIDE + aseg) * 2;                         \
                *(uint4*)(bp + OFF_BH + off) = rBh[i];                            \
                *(uint4*)(bp + OFF_BL + off) = rBl[i];                            \
            }                                                                     \
        }                                                                         \
    } while (0)

    LDG_CHUNK(0);
    STS_CHUNK(0);
    __syncthreads();

    for (int ch = 0; ch < NCH; ch++) {
        if (ch + 1 < NCH) LDG_CHUNK((ch + 1) * 32);

        // ---- compute on buffer ch&1
        {
            const char* bp = sm + (ch & 1) * STG_BYTES;
            const uint32_t* A32h = (const uint32_t*)(bp + OFF_AH);
            const uint32_t* A32l = (const uint32_t*)(bp + OFF_AL);
            const uint32_t* B32h = (const uint32_t*)(bp + OFF_BH);
            const uint32_t* B32l = (const uint32_t*)(bp + OFF_BL);
            #pragma unroll
            for (int ko = 0; ko < 2; ko++) {
                const int cb = ko * 8 + tig;   // u32 col
                uint32_t ah[4][4], al[4][4], bh[4][2], bl[4][2];
                #pragma unroll
                for (int mt = 0; mt < 4; mt++) {
                    int rr = (wm * 64 + mt * 16 + g) * (TILE_STRIDE / 2) + cb;
                    ah[mt][0] = A32h[rr];
                    ah[mt][1] = A32h[rr + 8 * (TILE_STRIDE / 2)];
                    ah[mt][2] = A32h[rr + 4];
                    ah[mt][3] = A32h[rr + 8 * (TILE_STRIDE / 2) + 4];
                    al[mt][0] = A32l[rr];
                    al[mt][1] = A32l[rr + 8 * (TILE_STRIDE / 2)];
                    al[mt][2] = A32l[rr + 4];
                    al[mt][3] = A32l[rr + 8 * (TILE_STRIDE / 2) + 4];
                }
                #pragma unroll
                for (int nt = 0; nt < 4; nt++) {
                    int rn = (wn * 32 + nt * 8 + g) * (TILE_STRIDE / 2) + cb;
                    bh[nt][0] = B32h[rn];
                    bh[nt][1] = B32h[rn + 4];
                    bl[nt][0] = B32l[rn];
                    bl[nt][1] = B32l[rn + 4];
                }
                #pragma unroll
                for (int mt = 0; mt < 4; mt++)
                    #pragma unroll
                    for (int nt = 0; nt < 4; nt++) {
                        mma16816(acc[mt][nt], ah[mt], bh[nt]);
                        mma16816(acc[mt][nt], ah[mt], bl[nt]);
                        mma16816(acc[mt][nt], al[mt], bh[nt]);
                    }
            }
        }

        if (ch + 1 < NCH) STS_CHUNK((ch + 1) & 1);
        __syncthreads();
    }
#undef LDG_CHUNK
#undef STS_CHUNK

    // ---- epilogue: + bias, store Y row-major fp32
    #pragma unroll
    for (int mt = 0; mt < 4; mt++) {
        int row = r0 + wm * 64 + mt * 16 + g;
        #pragma unroll
        for (int nt = 0; nt < 4; nt++) {
            int col = n0 + wn * 32 + nt * 8 + 2 * tig;
            float bv0 = __ldg(bias + col), bv1 = __ldg(bias + col + 1);
            float2 o0 = make_float2(acc[mt][nt][0] + bv0, acc[mt][nt][1] + bv1);
            float2 o1 = make_float2(acc[mt][nt][2] + bv0, acc[mt][nt][3] + bv1);
            *(float2*)&Y[(size_t)row * NO + col]       = o0;
            *(float2*)&Y[(size_t)(row + 8) * NO + col] = o1;
        }
    }
}

// ---------------- per-channel sum / sumsq over rows (device globals only!) ----------------
template<bool FIRST>
__global__ void k_stats() {
    constexpr int C = FIRST ? O1_ : O2_;
    const float* __restrict__ Y = FIRST ? g_Y1 : g_Y2;
    float* __restrict__ stats   = FIRST ? g_stats1 : g_stats2;
    int c = threadIdx.x;                      // blockDim.x == C
    size_t r0 = (size_t)blockIdx.x * 256;
    const float* p = Y + r0 * C + c;
    float s = 0.f, q = 0.f;
    #pragma unroll 8
    for (int i = 0; i < 256; i++) {
        float v = p[(size_t)i * C];
        s += v; q += v * v;
    }
    atomicAdd(&stats[c], s);
    atomicAdd(&stats[C + c], q);
}

// ---------------- finalize BN params ----------------
template<bool FIRST>
__global__ void k_fin(const float* __restrict__ g, const float* __restrict__ be) {
    constexpr int C = FIRST ? O1_ : O2_;
    int c = threadIdx.x;
    if (c < C) {
        const float* stats = FIRST ? g_stats1 : g_stats2;
        float mean = stats[c] * (1.0f / ROWS_);
        float var  = stats[C + c] * (1.0f / ROWS_) - mean * mean;
        float rstd = rsqrtf(var + BN_EPS_);
        float s = g[c] * rstd;
        if (FIRST) { g_sc1[c] = s; g_sh1[c] = be[c] - mean * s; }
        else       { g_sc2[c] = s; g_sh2[c] = be[c] - mean * s; }
    }
}

// ---------------- BN2 + ReLU + transpose to output [B][128][N] ----------------
__global__ void k_out(float* __restrict__ out) {
    __shared__ float tile[32][33];
    int b = blockIdx.z;
    int n0 = blockIdx.x * 32, o0 = blockIdx.y * 32;
    int tx = threadIdx.x, ty = threadIdx.y;
    float sc = g_sc2[o0 + tx], sh = g_sh2[o0 + tx];
    const float* src = g_Y2 + ((size_t)(b * N_ + n0)) * O2_ + o0;
    #pragma unroll
    for (int i = ty; i < 32; i += 8) {
        float v = src[(size_t)i * O2_ + tx];
        tile[i][tx] = fmaxf(fmaf(v, sc, sh), 0.f);
    }
    __syncthreads();
    float* dst = out + ((size_t)b * O2_ + o0) * N_ + n0;
    #pragma unroll
    for (int i = ty; i < 32; i += 8)
        dst[(size_t)i * N_ + tx] = tile[tx][i];
}

// ---------------- launch ----------------
extern "C" void kernel_launch(void* const* d_in, const int* in_sizes, int n_in,
                              void* d_out, int out_size) {
    (void)in_sizes; (void)n_in; (void)out_size;
    const float* xyz1    = (const float*)d_in[0];
    const float* xyz2    = (const float*)d_in[1];
    const float* points1 = (const float*)d_in[2];
    const float* points2 = (const float*)d_in[3];
    const float* w1  = (const float*)d_in[4];
    const float* b1  = (const float*)d_in[5];
    const float* g1  = (const float*)d_in[6];
    const float* be1 = (const float*)d_in[7];
    const float* w2  = (const float*)d_in[8];
    const float* b2  = (const float*)d_in[9];
    const float* g2  = (const float*)d_in[10];
    const float* be2 = (const float*)d_in[11];
    float* out = (float*)d_out;

    const int SMEM = 2 * STG_BYTES;   // 81920
    cudaFuncSetAttribute(k_gemm_mma<true>,  cudaFuncAttributeMaxDynamicSharedMemorySize, SMEM);
    cudaFuncSetAttribute(k_gemm_mma<false>, cudaFuncAttributeMaxDynamicSharedMemorySize, SMEM);

    k_pre<<<384, 256>>>(xyz2, w1, w2);
    k_tr_f2<<<dim3(S_ / 32, D2_ / 32, B_), dim3(32, 8)>>>(points2);
    k_tr_f1<<<dim3(N_ / 32, D1_ / 32, B_), dim3(32, 8)>>>(points1);
    k_nn3p<<<dim3(N_ / 256, B_, NPART), 256>>>(xyz1);
    k_merge<<<ROWS_ / 256, 256>>>(xyz1);
    k_interp<<<ROWS_ / 4, 256>>>();
    k_gemm_mma<true><<<dim3(ROWS_ / 128, 2), 256, SMEM>>>(b1);
    k_stats<true><<<ROWS_ / 256, O1_>>>();
    k_fin<true><<<1, 256>>>(g1, be1);
    k_gemm_mma<false><<<dim3(ROWS_ / 128, 1), 256, SMEM>>>(b2);
    k_stats<false><<<ROWS_ / 256, O2_>>>();
    k_fin<false><<<1, 128>>>(g2, be2);
    k_out<<<dim3(N_ / 32, O2_ / 32, B_), dim3(32, 8)>>>(out);
}

// round 6
// speedup vs baseline: 1.4546x; 1.0736x over previous
#include <cuda_runtime.h>
#include <cuda_bf16.h>
#include <cstdint>

// Problem constants
#define B_    8
#define N_    8192
#define S_    2048
#define D1_   128
#define D2_   256
#define C0_   384          // D1 + D2
#define O1_   256
#define O2_   128
#define ROWS_ 65536        // B_ * N_
#define BN_EPS_ 1e-5f
#define NPART 4
#define SPART (S_ / NPART)   // 512

// ---------------- device scratch (no cudaMalloc allowed) ----------------
__device__ __align__(16) __nv_bfloat16 g_Xh[(size_t)ROWS_ * C0_];  // concat hi
__device__ __align__(16) __nv_bfloat16 g_Xl[(size_t)ROWS_ * C0_];  // concat lo
__device__ __align__(16) float g_Y1[(size_t)ROWS_ * O1_];   // layer1 pre-BN
__device__ __align__(16) float g_Y2[(size_t)ROWS_ * O2_];   // layer2 pre-BN
__device__ __align__(16) float g_f2[(size_t)B_ * S_ * D2_]; // points2 transposed [b][s][d]
__device__ float4 g_p2[B_ * S_];                            // (x,y,z,|p|^2)
__device__ __align__(16) float g_cd[(size_t)ROWS_ * 12];    // split-NN candidate dists
__device__ __align__(16) int   g_ci[(size_t)ROWS_ * 12];    // split-NN candidate idx
__device__ int    g_idx3[ROWS_ * 3];
__device__ float  g_w3 [ROWS_ * 3];
__device__ float  g_stats1[2 * O1_];
__device__ float  g_stats2[2 * O2_];
__device__ float  g_sc1[O1_], g_sh1[O1_];
__device__ float  g_sc2[O2_], g_sh2[O2_];
__device__ __align__(16) __nv_bfloat16 g_w1h[O1_ * C0_], g_w1l[O1_ * C0_];
__device__ __align__(16) __nv_bfloat16 g_w2h[O2_ * O1_], g_w2l[O2_ * O1_];

// ---------------- helpers ----------------
__device__ __forceinline__ void bsplit2(float a, float b, uint32_t& h, uint32_t& l) {
    __nv_bfloat162 hv, lv;
    hv.x = __float2bfloat16_rn(a);
    hv.y = __float2bfloat16_rn(b);
    lv.x = __float2bfloat16_rn(a - __bfloat162float(hv.x));
    lv.y = __float2bfloat16_rn(b - __bfloat162float(hv.y));
    h = *reinterpret_cast<uint32_t*>(&hv);
    l = *reinterpret_cast<uint32_t*>(&lv);
}

// baseline-PTX HMMA: m16n8k16 bf16 x bf16 -> fp32
__device__ __forceinline__ void mma16816(float c[4], const uint32_t a[4],
                                         uint32_t b0, uint32_t b1) {
    asm volatile(
        "mma.sync.aligned.m16n8k16.row.col.f32.bf16.bf16.f32 "
        "{%0,%1,%2,%3}, {%4,%5,%6,%7}, {%8,%9}, {%0,%1,%2,%3};"
        : "+f"(c[0]), "+f"(c[1]), "+f"(c[2]), "+f"(c[3])
        : "r"(a[0]), "r"(a[1]), "r"(a[2]), "r"(a[3]), "r"(b0), "r"(b1));
}

// ldmatrix x4 (sm_75+ baseline)
__device__ __forceinline__ void ldsm4(uint32_t r[4], uint32_t addr) {
    asm volatile("ldmatrix.sync.aligned.m8n8.x4.shared.b16 {%0,%1,%2,%3}, [%4];"
        : "=r"(r[0]), "=r"(r[1]), "=r"(r[2]), "=r"(r[3]) : "r"(addr));
}

// ---------------- prep: stats zero + xyz2 pack + weight bf16 split ----------------
__global__ void k_pre(const float* __restrict__ xyz2,
                      const float* __restrict__ w1, const float* __restrict__ w2) {
    int t = blockIdx.x * 256 + threadIdx.x;
    if (t < 2 * O1_) g_stats1[t] = 0.f;
    if (t < 2 * O2_) g_stats2[t] = 0.f;
    if (t < B_ * S_) {
        int b = t / S_, s = t % S_;
        const float* p = xyz2 + (size_t)b * 3 * S_;
        float x = p[s], y = p[S_ + s], z = p[2 * S_ + s];
        g_p2[t] = make_float4(x, y, z, x * x + y * y + z * z);
    }
    if (t < O1_ * C0_) {
        float v = w1[t];
        __nv_bfloat16 h = __float2bfloat16_rn(v);
        g_w1h[t] = h;
        g_w1l[t] = __float2bfloat16_rn(v - __bfloat162float(h));
    }
    if (t < O2_ * O1_) {
        float v = w2[t];
        __nv_bfloat16 h = __float2bfloat16_rn(v);
        g_w2h[t] = h;
        g_w2l[t] = __float2bfloat16_rn(v - __bfloat162float(h));
    }
}

// ---------------- transpose points2 [B][D2][S] -> g_f2 [B][S][D2] ----------------
__global__ void k_tr_f2(const float* __restrict__ p2) {
    __shared__ float tile[32][33];
    int b = blockIdx.z;
    int s0 = blockIdx.x * 32, d0 = blockIdx.y * 32;
    int tx = threadIdx.x, ty = threadIdx.y;
    const float* src = p2 + ((size_t)b * D2_ + d0) * S_ + s0;
    #pragma unroll
    for (int i = ty; i < 32; i += 8)
        tile[i][tx] = src[(size_t)i * S_ + tx];
    __syncthreads();
    float* dst = g_f2 + ((size_t)b * S_ + s0) * D2_ + d0;
    #pragma unroll
    for (int i = ty; i < 32; i += 8)
        dst[(size_t)i * D2_ + tx] = tile[tx][i];
}

// ---------------- transpose points1 [B][D1][N] -> split bf16 g_Xh/g_Xl[:, 0:128] ----------------
__global__ void k_tr_f1(const float* __restrict__ p1) {
    __shared__ float tile[32][33];
    int b = blockIdx.z;
    int n0 = blockIdx.x * 32, d0 = blockIdx.y * 32;
    int tx = threadIdx.x, ty = threadIdx.y;
    const float* src = p1 + ((size_t)b * D1_ + d0) * N_ + n0;
    #pragma unroll
    for (int i = ty; i < 32; i += 8)
        tile[i][tx] = src[(size_t)i * N_ + tx];
    __syncthreads();
    size_t base = ((size_t)(b * N_ + n0)) * C0_ + d0;
    #pragma unroll
    for (int i = ty; i < 32; i += 8) {
        float v = tile[tx][i];
        __nv_bfloat16 h = __float2bfloat16_rn(v);
        g_Xh[base + (size_t)i * C0_ + tx] = h;
        g_Xl[base + (size_t)i * C0_ + tx] = __float2bfloat16_rn(v - __bfloat162float(h));
    }
}

// ---------------- 3-NN split over S ----------------
__global__ __launch_bounds__(256) void k_nn3p(const float* __restrict__ xyz1) {
    __shared__ float4 sp[SPART];   // 8 KB
    int b = blockIdx.y, part = blockIdx.z;
    int n = blockIdx.x * 256 + threadIdx.x;
    for (int i = threadIdx.x; i < SPART; i += 256)
        sp[i] = g_p2[b * S_ + part * SPART + i];
    __syncthreads();

    const float* q = xyz1 + (size_t)b * 3 * N_;
    float x = q[n], y = q[N_ + n], z = q[2 * N_ + n];
    float nx = -2.f * x, ny = -2.f * y, nz = -2.f * z;

    float d0 = 1e30f, d1 = 1e30f, d2 = 1e30f;
    int i0 = 0, i1 = 0, i2 = 0;
    #pragma unroll 8
    for (int s = 0; s < SPART; s++) {
        float4 p = sp[s];
        float d = fmaf(p.x, nx, fmaf(p.y, ny, fmaf(p.z, nz, p.w)));
        if (d < d2) {
            if (d < d1) {
                d2 = d1; i2 = i1;
                if (d < d0) { d1 = d0; i1 = i0; d0 = d; i0 = s; }
                else        { d1 = d;  i1 = s; }
            } else { d2 = d; i2 = s; }
        }
    }
    size_t row = (size_t)b * N_ + n;
    size_t o = row * 12 + part * 3;
    int base = part * SPART;
    g_cd[o + 0] = d0; g_cd[o + 1] = d1; g_cd[o + 2] = d2;
    g_ci[o + 0] = base + i0; g_ci[o + 1] = base + i1; g_ci[o + 2] = base + i2;
}

// ---------------- merge 12 candidates -> final top-3 + weights ----------------
__global__ void k_merge(const float* __restrict__ xyz1) {
    int t = blockIdx.x * 256 + threadIdx.x;
    int b = t / N_, n = t % N_;
    float d0 = 1e30f, d1 = 1e30f, d2 = 1e30f;
    int i0 = 0, i1 = 0, i2 = 0;
    const float* cd = g_cd + (size_t)t * 12;
    const int*   ci = g_ci + (size_t)t * 12;
    #pragma unroll
    for (int j = 0; j < 12; j++) {
        float d = cd[j]; int ix = ci[j];
        if (d < d2) {
            if (d < d1) {
                d2 = d1; i2 = i1;
                if (d < d0) { d1 = d0; i1 = i0; d0 = d; i0 = ix; }
                else        { d1 = d;  i1 = ix; }
            } else { d2 = d; i2 = ix; }
        }
    }
    const float* q = xyz1 + (size_t)b * 3 * N_;
    float x = q[n], y = q[N_ + n], z = q[2 * N_ + n];
    float r1 = x * x + y * y + z * z;
    float t0 = fmaxf(d0 + r1, 1e-10f);
    float t1 = fmaxf(d1 + r1, 1e-10f);
    float t2 = fmaxf(d2 + r1, 1e-10f);
    float w0 = 1.f / t0, w1 = 1.f / t1, w2 = 1.f / t2;
    float inv = 1.f / (w0 + w1 + w2);
    g_idx3[(size_t)t * 3 + 0] = i0; g_idx3[(size_t)t * 3 + 1] = i1; g_idx3[(size_t)t * 3 + 2] = i2;
    g_w3 [(size_t)t * 3 + 0] = w0 * inv;
    g_w3 [(size_t)t * 3 + 1] = w1 * inv;
    g_w3 [(size_t)t * 3 + 2] = w2 * inv;
}

// ---------------- gather + interpolate (float4) -> split bf16 ----------------
__global__ __launch_bounds__(256) void k_interp() {
    int t = threadIdx.x;
    int lr = t >> 6, ln = t & 63;
    unsigned row = blockIdx.x * 4 + lr;
    int b = row / N_;
    int  i0 = g_idx3[(size_t)row * 3 + 0];
    int  i1 = g_idx3[(size_t)row * 3 + 1];
    int  i2 = g_idx3[(size_t)row * 3 + 2];
    float w0 = g_w3[(size_t)row * 3 + 0];
    float w1 = g_w3[(size_t)row * 3 + 1];
    float w2 = g_w3[(size_t)row * 3 + 2];
    const float4* f = (const float4*)(g_f2 + (size_t)b * S_ * D2_);
    float4 v0 = f[(size_t)i0 * 64 + ln];
    float4 v1 = f[(size_t)i1 * 64 + ln];
    float4 v2 = f[(size_t)i2 * 64 + ln];
    float4 v;
    v.x = w0 * v0.x + w1 * v1.x + w2 * v2.x;
    v.y = w0 * v0.y + w1 * v1.y + w2 * v2.y;
    v.z = w0 * v0.z + w1 * v1.z + w2 * v2.z;
    v.w = w0 * v0.w + w1 * v1.w + w2 * v2.w;
    uint2 hq, lq;
    bsplit2(v.x, v.y, hq.x, lq.x);
    bsplit2(v.z, v.w, hq.y, lq.y);
    size_t o = (size_t)row * C0_ + D1_ + ln * 4;
    *(uint2*)&g_Xh[o] = hq;
    *(uint2*)&g_Xl[o] = lq;
}

// ---------------- HMMA bf16-split GEMM with ldmatrix + fused BN stats ----------------
// CTA 128x128, 8 warps (2x4) of 64x32, k-chunk 32, double-buffered smem.
// smem rows padded to 40 bf16 (80 B): ldmatrix 8-row phases hit all 32 banks.
#define TILE_STRIDE 40
#define OFF_AH 0
#define OFF_AL 10240
#define OFF_BH 20480
#define OFF_BL 30720
#define STG_BYTES 40960

template<bool FIRST>
__global__ __launch_bounds__(256, 1) void k_gemm_mma(const float* __restrict__ bias) {
    constexpr int KD = FIRST ? C0_ : O1_;
    constexpr int NO = FIRST ? O1_ : O2_;
    constexpr int NCH = KD / 32;

    const __nv_bfloat16* __restrict__ Wh = FIRST ? g_w1h : g_w2h;
    const __nv_bfloat16* __restrict__ Wl = FIRST ? g_w1l : g_w2l;
    float* __restrict__ Y     = FIRST ? g_Y1 : g_Y2;
    float* __restrict__ stats = FIRST ? g_stats1 : g_stats2;

    extern __shared__ char sm[];
    const uint32_t smbase = (uint32_t)__cvta_generic_to_shared(sm);

    const int tid = threadIdx.x;
    const int lane = tid & 31, wid = tid >> 5;
    const int g = lane >> 2, tig = lane & 3;
    const int wm = wid & 1, wn = wid >> 1;
    const int r0 = blockIdx.x * 128;
    const int n0 = blockIdx.y * 128;

    float acc[4][4][4];
    #pragma unroll
    for (int m = 0; m < 4; m++)
        #pragma unroll
        for (int n = 0; n < 4; n++)
            #pragma unroll
            for (int j = 0; j < 4; j++) acc[m][n][j] = 0.f;

    // ldmatrix per-thread source offsets (bytes within a tile region)
    // A/B x4: row = base + (lane&15) [A] / base + ((lane>>4)<<3)+(lane&7) [B]
    const uint32_t a_off = (uint32_t)((wm * 64 + (lane & 15)) * TILE_STRIDE * 2 + (lane >> 4) * 16);
    const uint32_t b_row = (uint32_t)(((lane >> 4) << 3) + (lane & 7));
    const uint32_t b_off0 = (uint32_t)((wn * 32 + b_row) * TILE_STRIDE * 2 + ((lane >> 3) & 1) * 16);
    const uint32_t b_off1 = (uint32_t)((wn * 32 + 16 + b_row) * TILE_STRIDE * 2 + ((lane >> 3) & 1) * 16);

    // ---- per-thread LDG indices
    const int arow = tid >> 2, aseg = (tid & 3) * 8;
    const int frow = tid >> 1, fhalf = (tid & 1) * 16;

    uint4 rAh[2], rAl[2], rBh[2], rBl[2];

#define LDG_CHUNK(kc) do {                                                        \
        if (FIRST) {                                                              \
            _Pragma("unroll")                                                     \
            for (int i = 0; i < 2; i++) {                                         \
                int row = arow + i * 64;                                          \
                rAh[i] = *(const uint4*)&g_Xh[(size_t)(r0 + row) * C0_ + (kc) + aseg]; \
                rAl[i] = *(const uint4*)&g_Xl[(size_t)(r0 + row) * C0_ + (kc) + aseg]; \
                rBh[i] = *(const uint4*)&Wh[(size_t)(n0 + row) * KD + (kc) + aseg];    \
                rBl[i] = *(const uint4*)&Wl[(size_t)(n0 + row) * KD + (kc) + aseg];    \
            }                                                                     \
        } else {                                                                  \
            const float* ap = g_Y1 + (size_t)(r0 + frow) * O1_ + (kc) + fhalf;    \
            const float* scp = g_sc1 + (kc) + fhalf;                              \
            const float* shp = g_sh1 + (kc) + fhalf;                              \
            _Pragma("unroll")                                                     \
            for (int i = 0; i < 2; i++) {                                         \
                float4 u = *(const float4*)(ap + i * 8);                          \
                float4 v = *(const float4*)(ap + i * 8 + 4);                      \
                float4 scu = *(const float4*)(scp + i * 8);                       \
                float4 shu = *(const float4*)(shp + i * 8);                       \
                float4 scv = *(const float4*)(scp + i * 8 + 4);                   \
                float4 shv = *(const float4*)(shp + i * 8 + 4);                   \
                u.x = fmaxf(fmaf(u.x, scu.x, shu.x), 0.f);                        \
                u.y = fmaxf(fmaf(u.y, scu.y, shu.y), 0.f);                        \
                u.z = fmaxf(fmaf(u.z, scu.z, shu.z), 0.f);                        \
                u.w = fmaxf(fmaf(u.w, scu.w, shu.w), 0.f);                        \
                v.x = fmaxf(fmaf(v.x, scv.x, shv.x), 0.f);                        \
                v.y = fmaxf(fmaf(v.y, scv.y, shv.y), 0.f);                        \
                v.z = fmaxf(fmaf(v.z, scv.z, shv.z), 0.f);                        \
                v.w = fmaxf(fmaf(v.w, scv.w, shv.w), 0.f);                        \
                bsplit2(u.x, u.y, rAh[i].x, rAl[i].x);                            \
                bsplit2(u.z, u.w, rAh[i].y, rAl[i].y);                            \
                bsplit2(v.x, v.y, rAh[i].z, rAl[i].z);                            \
                bsplit2(v.z, v.w, rAh[i].w, rAl[i].w);                            \
            }                                                                     \
            _Pragma("unroll")                                                     \
            for (int i = 0; i < 2; i++) {                                         \
                int row = arow + i * 64;                                          \
                rBh[i] = *(const uint4*)&Wh[(size_t)(n0 + row) * KD + (kc) + aseg];    \
                rBl[i] = *(const uint4*)&Wl[(size_t)(n0 + row) * KD + (kc) + aseg];    \
            }                                                                     \
        }                                                                         \
    } while (0)

#define STS_CHUNK(buf) do {                                                       \
        char* bp = sm + (buf) * STG_BYTES;                                        \
        if (FIRST) {                                                              \
            _Pragma("unroll")                                                     \
            for (int i = 0; i < 2; i++) {                                         \
                int row = arow + i * 64;                                          \
                int off = (row * TILE_STRIDE + aseg) * 2;                         \
                *(uint4*)(bp + OFF_AH + off) = rAh[i];                            \
                *(uint4*)(bp + OFF_AL + off) = rAl[i];                            \
                *(uint4*)(bp + OFF_BH + off) = rBh[i];                            \
                *(uint4*)(bp + OFF_BL + off) = rBl[i];                            \
            }                                                                     \
        } else {                                                                  \
            int offa = (frow * TILE_STRIDE + fhalf) * 2;                          \
            *(uint4*)(bp + OFF_AH + offa)      = rAh[0];                          \
            *(uint4*)(bp + OFF_AH + offa + 16) = rAh[1];                          \
            *(uint4*)(bp + OFF_AL + offa)      = rAl[0];                          \
            *(uint4*)(bp + OFF_AL + offa + 16) = rAl[1];                          \
            _Pragma("unroll")                                                     \
            for (int i = 0; i < 2; i++) {                                         \
                int row = arow + i * 64;                                          \
                int off = (row * TILE_STRIDE + aseg) * 2;                         \
                *(uint4*)(bp + OFF_BH + off) = rBh[i];                            \
                *(uint4*)(bp + OFF_BL + off) = rBl[i];                            \
            }                                                                     \
        }                                                                         \
    } while (0)

    LDG_CHUNK(0);
    STS_CHUNK(0);
    __syncthreads();

    for (int ch = 0; ch < NCH; ch++) {
        if (ch + 1 < NCH) LDG_CHUNK((ch + 1) * 32);

        {
            const uint32_t bufb = smbase + (uint32_t)((ch & 1) * STG_BYTES);
            #pragma unroll
            for (int ko = 0; ko < 2; ko++) {
                const uint32_t kb = (uint32_t)(ko * 32);
                uint32_t ah[4][4], al[4][4], bh01[4], bl01[4], bh23[4], bl23[4];
                #pragma unroll
                for (int mt = 0; mt < 4; mt++) {
                    uint32_t ao = bufb + a_off + (uint32_t)(mt * 16 * TILE_STRIDE * 2) + kb;
                    ldsm4(ah[mt], ao + OFF_AH);
                    ldsm4(al[mt], ao + OFF_AL);
                }
                ldsm4(bh01, bufb + OFF_BH + b_off0 + kb);
                ldsm4(bl01, bufb + OFF_BL + b_off0 + kb);
                ldsm4(bh23, bufb + OFF_BH + b_off1 + kb);
                ldsm4(bl23, bufb + OFF_BL + b_off1 + kb);

                #pragma unroll
                for (int mt = 0; mt < 4; mt++) {
                    mma16816(acc[mt][0], ah[mt], bh01[0], bh01[1]);
                    mma16816(acc[mt][0], ah[mt], bl01[0], bl01[1]);
                    mma16816(acc[mt][0], al[mt], bh01[0], bh01[1]);
                    mma16816(acc[mt][1], ah[mt], bh01[2], bh01[3]);
                    mma16816(acc[mt][1], ah[mt], bl01[2], bl01[3]);
                    mma16816(acc[mt][1], al[mt], bh01[2], bh01[3]);
                    mma16816(acc[mt][2], ah[mt], bh23[0], bh23[1]);
                    mma16816(acc[mt][2], ah[mt], bl23[0], bl23[1]);
                    mma16816(acc[mt][2], al[mt], bh23[0], bh23[1]);
                    mma16816(acc[mt][3], ah[mt], bh23[2], bh23[3]);
                    mma16816(acc[mt][3], ah[mt], bl23[2], bl23[3]);
                    mma16816(acc[mt][3], al[mt], bh23[2], bh23[3]);
                }
            }
        }

        if (ch + 1 < NCH) STS_CHUNK((ch + 1) & 1);
        __syncthreads();
    }
#undef LDG_CHUNK
#undef STS_CHUNK

    // ---- epilogue: + bias, store Y, fused per-channel BN stats
    float ssum[4][2], ssq[4][2];
    #pragma unroll
    for (int nt = 0; nt < 4; nt++) { ssum[nt][0] = ssum[nt][1] = 0.f; ssq[nt][0] = ssq[nt][1] = 0.f; }

    #pragma unroll
    for (int mt = 0; mt < 4; mt++) {
        int row = r0 + wm * 64 + mt * 16 + g;
        #pragma unroll
        for (int nt = 0; nt < 4; nt++) {
            int col = n0 + wn * 32 + nt * 8 + 2 * tig;
            float bv0 = __ldg(bias + col), bv1 = __ldg(bias + col + 1);
            float v0 = acc[mt][nt][0] + bv0, v1 = acc[mt][nt][1] + bv1;
            float v2 = acc[mt][nt][2] + bv0, v3 = acc[mt][nt][3] + bv1;
            ssum[nt][0] += v0 + v2;  ssum[nt][1] += v1 + v3;
            ssq[nt][0]  += v0 * v0 + v2 * v2;
            ssq[nt][1]  += v1 * v1 + v3 * v3;
            *(float2*)&Y[(size_t)row * NO + col]       = make_float2(v0, v1);
            *(float2*)&Y[(size_t)(row + 8) * NO + col] = make_float2(v2, v3);
        }
    }

    // reduce over g-lanes (xor 4,8,16 keeps tig fixed), then lanes g==0 do REDs
    #pragma unroll
    for (int nt = 0; nt < 4; nt++)
        #pragma unroll
        for (int c = 0; c < 2; c++) {
            float s = ssum[nt][c], q = ssq[nt][c];
            s += __shfl_xor_sync(0xFFFFFFFFu, s, 4);
            s += __shfl_xor_sync(0xFFFFFFFFu, s, 8);
            s += __shfl_xor_sync(0xFFFFFFFFu, s, 16);
            q += __shfl_xor_sync(0xFFFFFFFFu, q, 4);
            q += __shfl_xor_sync(0xFFFFFFFFu, q, 8);
            q += __shfl_xor_sync(0xFFFFFFFFu, q, 16);
            if (g == 0) {
                int col = n0 + wn * 32 + nt * 8 + 2 * tig + c;
                atomicAdd(&stats[col], s);
                atomicAdd(&stats[NO + col], q);
            }
        }
}

// ---------------- finalize BN params ----------------
template<bool FIRST>
__global__ void k_fin(const float* __restrict__ g, const float* __restrict__ be) {
    constexpr int C = FIRST ? O1_ : O2_;
    int c = threadIdx.x;
    if (c < C) {
        const float* stats = FIRST ? g_stats1 : g_stats2;
        float mean = stats[c] * (1.0f / ROWS_);
        float var  = stats[C + c] * (1.0f / ROWS_) - mean * mean;
        float rstd = rsqrtf(var + BN_EPS_);
        float s = g[c] * rstd;
        if (FIRST) { g_sc1[c] = s; g_sh1[c] = be[c] - mean * s; }
        else       { g_sc2[c] = s; g_sh2[c] = be[c] - mean * s; }
    }
}

// ---------------- BN2 + ReLU + transpose to output [B][128][N] ----------------
__global__ void k_out(float* __restrict__ out) {
    __shared__ float tile[32][33];
    int b = blockIdx.z;
    int n0 = blockIdx.x * 32, o0 = blockIdx.y * 32;
    int tx = threadIdx.x, ty = threadIdx.y;
    float sc = g_sc2[o0 + tx], sh = g_sh2[o0 + tx];
    const float* src = g_Y2 + ((size_t)(b * N_ + n0)) * O2_ + o0;
    #pragma unroll
    for (int i = ty; i < 32; i += 8) {
        float v = src[(size_t)i * O2_ + tx];
        tile[i][tx] = fmaxf(fmaf(v, sc, sh), 0.f);
    }
    __syncthreads();
    float* dst = out + ((size_t)b * O2_ + o0) * N_ + n0;
    #pragma unroll
    for (int i = ty; i < 32; i += 8)
        dst[(size_t)i * N_ + tx] = tile[tx][i];
}

// ---------------- launch ----------------
extern "C" void kernel_launch(void* const* d_in, const int* in_sizes, int n_in,
                              void* d_out, int out_size) {
    (void)in_sizes; (void)n_in; (void)out_size;
    const float* xyz1    = (const float*)d_in[0];
    const float* xyz2    = (const float*)d_in[1];
    const float* points1 = (const float*)d_in[2];
    const float* points2 = (const float*)d_in[3];
    const float* w1  = (const float*)d_in[4];
    const float* b1  = (const float*)d_in[5];
    const float* g1  = (const float*)d_in[6];
    const float* be1 = (const float*)d_in[7];
    const float* w2  = (const float*)d_in[8];
    const float* b2  = (const float*)d_in[9];
    const float* g2  = (const float*)d_in[10];
    const float* be2 = (const float*)d_in[11];
    float* out = (float*)d_out;

    const int SMEM = 2 * STG_BYTES;   // 81920
    cudaFuncSetAttribute(k_gemm_mma<true>,  cudaFuncAttributeMaxDynamicSharedMemorySize, SMEM);
    cudaFuncSetAttribute(k_gemm_mma<false>, cudaFuncAttributeMaxDynamicSharedMemorySize, SMEM);

    k_pre<<<384, 256>>>(xyz2, w1, w2);
    k_tr_f2<<<dim3(S_ / 32, D2_ / 32, B_), dim3(32, 8)>>>(points2);
    k_tr_f1<<<dim3(N_ / 32, D1_ / 32, B_), dim3(32, 8)>>>(points1);
    k_nn3p<<<dim3(N_ / 256, B_, NPART), 256>>>(xyz1);
    k_merge<<<ROWS_ / 256, 256>>>(xyz1);
    k_interp<<<ROWS_ / 4, 256>>>();
    k_gemm_mma<true><<<dim3(ROWS_ / 128, 2), 256, SMEM>>>(b1);
    k_fin<true><<<1, 256>>>(g1, be1);
    k_gemm_mma<false><<<dim3(ROWS_ / 128, 1), 256, SMEM>>>(b2);
    k_fin<false><<<1, 128>>>(g2, be2);
    k_out<<<dim3(N_ / 32, O2_ / 32, B_), dim3(32, 8)>>>(out);
}